// round 8
// baseline (speedup 1.0000x reference)
#include <cuda_runtime.h>
#include <cuda_fp16.h>
#include <cstdint>

// ---------------- problem constants ----------------
#define NIN   4096
#define NOUT  1024
#define BC    128          // B*C = 4*32
#define C_DIM 32

// GEMM: D[o(1024), bc(128)] = sum_k M[o,k] * gftT[bc,k]
#define KSPLIT 16
#define KPB    (NIN / KSPLIT)   // 256
#define KC     64               // k per smem chunk
#define NCHUNK (KPB / KC)       // 4
#define MTILES (NOUT / 128)     // 8
#define ROWH   72               // smem row stride in halves (64 + 16B pad)

// zero kernel coverage: M = 4M halves = 524288 uint4; out = 131072 f32 = 32768 uint4
#define ZVEC_M   524288
#define ZVEC_ALL (ZVEC_M + 32768)   // 557056 -> 2176 blocks x 256

// ---------------- device scratch ----------------
__device__ __align__(16) __half g_Mh[NOUT * NIN];  // 8.4 MB count matrix (fp16)
__device__ __half g_ghi[BC * NIN];                 // 1 MB  (G@F)^T hi (fp16)
__device__ __half g_glo[BC * NIN];                 // 1 MB  (G@F)^T lo (fp16)

__device__ __forceinline__ uint32_t smem_u32(const void* p) {
    uint32_t a;
    asm("{ .reg .u64 t; cvta.to.shared.u64 t, %1; cvt.u32.u64 %0, t; }" : "=r"(a) : "l"(p));
    return a;
}

__device__ __forceinline__ void ldsm_x4(uint32_t* r, uint32_t addr) {
    asm volatile("ldmatrix.sync.aligned.m8n8.x4.shared.b16 {%0,%1,%2,%3}, [%4];"
                 : "=r"(r[0]), "=r"(r[1]), "=r"(r[2]), "=r"(r[3]) : "r"(addr));
}

__device__ __forceinline__ void mma16816(float* c, const uint32_t* a,
                                         uint32_t b0, uint32_t b1) {
    asm volatile(
        "mma.sync.aligned.m16n8k16.row.col.f32.f16.f16.f32 "
        "{%0,%1,%2,%3}, {%4,%5,%6,%7}, {%8,%9}, {%0,%1,%2,%3};"
        : "+f"(c[0]), "+f"(c[1]), "+f"(c[2]), "+f"(c[3])
        : "r"(a[0]), "r"(a[1]), "r"(a[2]), "r"(a[3]), "r"(b0), "r"(b1));
}

// ---------------------------------------------------------------------------
// Kernel 0: wide-grid zeroing of M (fp16) and out. One uint4 per thread.
// ---------------------------------------------------------------------------
__global__ void qc_zero(float* __restrict__ out) {
    int gt = blockIdx.x * 256 + threadIdx.x;
    uint4 z = make_uint4(0u, 0u, 0u, 0u);
    if (gt < ZVEC_M)
        reinterpret_cast<uint4*>(g_Mh)[gt] = z;
    else
        reinterpret_cast<uint4*>(out)[gt - ZVEC_M] = z;
}

// ---------------------------------------------------------------------------
// Kernel 1: fused channel-GEMM producing gftT hi/lo (fp16 split).
// gftT[b*32+oc][n] = sum_i G[oc,i]*F[b,i,n].  Grid = 64 (4 b x 16 n-tiles).
// ---------------------------------------------------------------------------
__global__ void qc_transform(const float* __restrict__ F,
                             const float* __restrict__ G) {
    __shared__ float Fs[C_DIM * 256];
    __shared__ float Gs[C_DIM * 33];
    int t  = threadIdx.x;
    int b  = blockIdx.x >> 4;
    int n0 = (blockIdx.x & 15) * 256;

    #pragma unroll
    for (int j = 0; j < 32; j++) {
        int idx = t + j * 256;                       // idx = i*256 + nl
        Fs[idx] = F[b * (C_DIM * NIN) + (idx >> 8) * NIN + n0 + (idx & 255)];
    }
    #pragma unroll
    for (int j = 0; j < 4; j++) {
        int idx = t + j * 256;
        Gs[(idx >> 5) * 33 + (idx & 31)] = G[idx];
    }
    __syncthreads();

    #pragma unroll 4
    for (int oc = 0; oc < 32; oc++) {
        float s = 0.f;
        #pragma unroll
        for (int i = 0; i < 32; i++)
            s = fmaf(Gs[oc * 33 + i], Fs[i * 256 + t], s);
        __half h = __float2half_rn(s);
        __half l = __float2half_rn(s - __half2float(h));
        int row = b * 32 + oc;
        g_ghi[row * NIN + n0 + t] = h;
        g_glo[row * NIN + n0 + t] = l;
    }
}

// ---------------------------------------------------------------------------
// Kernel 2: build count matrix. Thread per edge, spread fp16 atomics (RED.F16).
// Counts are small integers -> exact in fp16.
// ---------------------------------------------------------------------------
__global__ void qc_count(const int* __restrict__ idx_out,
                         const int* __restrict__ idx_in, int E) {
    int e = blockIdx.x * blockDim.x + threadIdx.x;
    if (e >= E) return;
    atomicAdd(&g_Mh[idx_out[e] * NIN + idx_in[e]], __float2half(1.0f));
}

// ---------------------------------------------------------------------------
// Kernel 3: HMMA GEMM. Block = 256 threads (8 warps, 4x2), D tile 128o x 128bc,
// K range KPB=256 in 4 chunks of 64. A = M (fp16 direct), B = hi & lo,
// accumulating into f32 fragments. Epilogue RED-adds into out (bc-major).
// ---------------------------------------------------------------------------
__global__ void __launch_bounds__(256, 1) qc_gemm_mma(float* __restrict__ out) {
    extern __shared__ __half sm[];
    __half* As = sm;                 // 128 x ROWH
    __half* Bh = sm + 128 * ROWH;    // 128 x ROWH
    __half* Bl = sm + 256 * ROWH;    // 128 x ROWH

    int t    = threadIdx.x;
    int wid  = t >> 5;
    int lane = t & 31;
    int mt_b = blockIdx.x & 7;
    int ks   = blockIdx.x >> 3;
    int o0   = mt_b * 128;
    int k0   = ks * KPB;
    int wo   = (wid >> 1) * 32;      // warp o offset (0/32/64/96)
    int n0w  = (wid & 1) * 64;       // warp bc offset (0/64)

    uint32_t sA = smem_u32(As), sBh = smem_u32(Bh), sBl = smem_u32(Bl);

    float acc[2][8][4];
    #pragma unroll
    for (int i = 0; i < 2; i++)
        #pragma unroll
        for (int j = 0; j < 8; j++)
            #pragma unroll
            for (int q = 0; q < 4; q++) acc[i][j][q] = 0.f;

    for (int c = 0; c < NCHUNK; c++) {
        int kc0 = k0 + c * KC;

        // A tile: fp16 M direct u32 copies (coalesced 128B/warp)
        #pragma unroll
        for (int j = 0; j < 16; j++) {
            int idx = t + j * 256;          // 0..4095
            int row = idx >> 5, cp = idx & 31;
            *reinterpret_cast<uint32_t*>(&As[row * ROWH + cp * 2]) =
                *reinterpret_cast<const uint32_t*>(
                    &g_Mh[(o0 + row) * NIN + kc0 + cp * 2]);
        }
        // B tiles hi/lo
        #pragma unroll
        for (int j = 0; j < 16; j++) {
            int idx = t + j * 256;
            int row = idx >> 5, cp = idx & 31;
            int gsrc = row * NIN + kc0 + cp * 2;
            int sdst = row * ROWH + cp * 2;
            *reinterpret_cast<uint32_t*>(&Bh[sdst]) =
                *reinterpret_cast<const uint32_t*>(&g_ghi[gsrc]);
            *reinterpret_cast<uint32_t*>(&Bl[sdst]) =
                *reinterpret_cast<const uint32_t*>(&g_glo[gsrc]);
        }
        __syncthreads();

        #pragma unroll
        for (int kk = 0; kk < KC; kk += 16) {
            uint32_t a[2][4];
            #pragma unroll
            for (int mt = 0; mt < 2; mt++)
                ldsm_x4(a[mt], sA + 2 * ((wo + mt * 16 + (lane & 15)) * ROWH
                                          + kk + (lane >> 4) * 8));
            #pragma unroll
            for (int h = 0; h < 2; h++) {
                uint32_t sB = h ? sBl : sBh;
                #pragma unroll
                for (int ng = 0; ng < 4; ng++) {
                    uint32_t b[4];
                    ldsm_x4(b, sB + 2 * ((n0w + ng * 16 + (lane & 15)) * ROWH
                                          + kk + (lane >> 4) * 8));
                    #pragma unroll
                    for (int mt = 0; mt < 2; mt++) {
                        mma16816(acc[mt][ng * 2 + 0], a[mt], b[0], b[2]);
                        mma16816(acc[mt][ng * 2 + 1], a[mt], b[1], b[3]);
                    }
                }
            }
        }
        __syncthreads();
    }

    // Epilogue: RED straight into out[bc*NOUT + o] (zeroed by qc_zero).
    #pragma unroll
    for (int mt = 0; mt < 2; mt++) {
        #pragma unroll
        for (int nt = 0; nt < 8; nt++) {
            int o  = o0 + wo + mt * 16 + (lane >> 2);
            int bc = n0w + nt * 8 + (lane & 3) * 2;
            atomicAdd(&out[bc * NOUT + o],             acc[mt][nt][0]);
            atomicAdd(&out[(bc + 1) * NOUT + o],       acc[mt][nt][1]);
            atomicAdd(&out[bc * NOUT + o + 8],         acc[mt][nt][2]);
            atomicAdd(&out[(bc + 1) * NOUT + o + 8],   acc[mt][nt][3]);
        }
    }
}

// ---------------------------------------------------------------------------
extern "C" void kernel_launch(void* const* d_in, const int* in_sizes, int n_in,
                              void* d_out, int out_size) {
    const float* features = (const float*)d_in[0];   // (4,32,4096) f32
    const float* G        = (const float*)d_in[1];   // (32,32)     f32
    const int*   idx_out  = (const int*)d_in[2];     // (E,) i32
    const int*   idx_in   = (const int*)d_in[3];     // (E,) i32
    float*       out      = (float*)d_out;           // (4,32,1024) f32
    int E = in_sizes[2];

    static const int GEMM_SMEM = 3 * 128 * ROWH * (int)sizeof(__half);  // 55296
    cudaFuncSetAttribute(qc_gemm_mma,
                         cudaFuncAttributeMaxDynamicSharedMemorySize, GEMM_SMEM);

    qc_zero<<<ZVEC_ALL / 256, 256>>>(out);
    qc_transform<<<64, 256>>>(features, G);
    qc_count<<<(E + 255) / 256, 256>>>(idx_out, idx_in, E);
    qc_gemm_mma<<<MTILES * KSPLIT, 256, GEMM_SMEM>>>(out);
}

// round 9
// speedup vs baseline: 1.0312x; 1.0312x over previous
#include <cuda_runtime.h>
#include <cuda_fp16.h>
#include <cstdint>

// ---------------- problem constants ----------------
#define NIN   4096
#define NOUT  1024
#define BC    128          // B*C = 4*32
#define C_DIM 32

// GEMM: D[o(1024), bc(128)] = sum_k M[o,k] * gftT[bc,k]
#define KSPLIT 16
#define KPB    (NIN / KSPLIT)   // 256
#define KC     64               // k per smem chunk
#define NCHUNK (KPB / KC)       // 4
#define MTILES (NOUT / 128)     // 8
#define ROWH   72               // smem row stride in halves (144B = 9x16B)
#define TILEH  (128 * ROWH)     // halves per tile buffer

// zero kernel coverage: M = 4M halves = 524288 uint4; out = 131072 f32 = 32768 uint4
#define ZVEC_M   524288
#define ZVEC_ALL (ZVEC_M + 32768)   // 557056 -> 2176 blocks x 256

// ---------------- device scratch ----------------
__device__ __align__(16) __half g_Mh[NOUT * NIN];  // 8.4 MB count matrix (fp16)
__device__ __align__(16) __half g_ghi[BC * NIN];   // 1 MB  (G@F)^T hi (fp16)
__device__ __align__(16) __half g_glo[BC * NIN];   // 1 MB  (G@F)^T lo (fp16)

__device__ __forceinline__ uint32_t smem_u32(const void* p) {
    uint32_t a;
    asm("{ .reg .u64 t; cvta.to.shared.u64 t, %1; cvt.u32.u64 %0, t; }" : "=r"(a) : "l"(p));
    return a;
}

__device__ __forceinline__ void cp16(uint32_t dst, const void* src) {
    asm volatile("cp.async.cg.shared.global [%0], [%1], 16;" :: "r"(dst), "l"(src));
}
__device__ __forceinline__ void cp_commit() {
    asm volatile("cp.async.commit_group;" ::: "memory");
}
__device__ __forceinline__ void cp_wait0() {
    asm volatile("cp.async.wait_group 0;" ::: "memory");
}

__device__ __forceinline__ void ldsm_x4(uint32_t* r, uint32_t addr) {
    asm volatile("ldmatrix.sync.aligned.m8n8.x4.shared.b16 {%0,%1,%2,%3}, [%4];"
                 : "=r"(r[0]), "=r"(r[1]), "=r"(r[2]), "=r"(r[3]) : "r"(addr));
}

__device__ __forceinline__ void mma16816(float* c, const uint32_t* a,
                                         uint32_t b0, uint32_t b1) {
    asm volatile(
        "mma.sync.aligned.m16n8k16.row.col.f32.f16.f16.f32 "
        "{%0,%1,%2,%3}, {%4,%5,%6,%7}, {%8,%9}, {%0,%1,%2,%3};"
        : "+f"(c[0]), "+f"(c[1]), "+f"(c[2]), "+f"(c[3])
        : "r"(a[0]), "r"(a[1]), "r"(a[2]), "r"(a[3]), "r"(b0), "r"(b1));
}

// ---------------------------------------------------------------------------
// Kernel 0: wide-grid zeroing of M (fp16) and out. One uint4 per thread.
// ---------------------------------------------------------------------------
__global__ void qc_zero(float* __restrict__ out) {
    int gt = blockIdx.x * 256 + threadIdx.x;
    uint4 z = make_uint4(0u, 0u, 0u, 0u);
    if (gt < ZVEC_M)
        reinterpret_cast<uint4*>(g_Mh)[gt] = z;
    else
        reinterpret_cast<uint4*>(out)[gt - ZVEC_M] = z;
}

// ---------------------------------------------------------------------------
// Kernel 1: fused channel-GEMM producing gftT hi/lo (fp16 split).
// gftT[b*32+oc][n] = sum_i G[oc,i]*F[b,i,n].  Grid = 64 (4 b x 16 n-tiles).
// ---------------------------------------------------------------------------
__global__ void qc_transform(const float* __restrict__ F,
                             const float* __restrict__ G) {
    __shared__ float Fs[C_DIM * 256];
    __shared__ float Gs[C_DIM * 33];
    int t  = threadIdx.x;
    int b  = blockIdx.x >> 4;
    int n0 = (blockIdx.x & 15) * 256;

    #pragma unroll
    for (int j = 0; j < 32; j++) {
        int idx = t + j * 256;                       // idx = i*256 + nl
        Fs[idx] = F[b * (C_DIM * NIN) + (idx >> 8) * NIN + n0 + (idx & 255)];
    }
    #pragma unroll
    for (int j = 0; j < 4; j++) {
        int idx = t + j * 256;
        Gs[(idx >> 5) * 33 + (idx & 31)] = G[idx];
    }
    __syncthreads();

    #pragma unroll 4
    for (int oc = 0; oc < 32; oc++) {
        float s = 0.f;
        #pragma unroll
        for (int i = 0; i < 32; i++)
            s = fmaf(Gs[oc * 33 + i], Fs[i * 256 + t], s);
        __half h = __float2half_rn(s);
        __half l = __float2half_rn(s - __half2float(h));
        int row = b * 32 + oc;
        g_ghi[row * NIN + n0 + t] = h;
        g_glo[row * NIN + n0 + t] = l;
    }
}

// ---------------------------------------------------------------------------
// Kernel 2: build count matrix. Thread per edge, spread fp16 atomics (RED.F16).
// ---------------------------------------------------------------------------
__global__ void qc_count(const int* __restrict__ idx_out,
                         const int* __restrict__ idx_in, int E) {
    int e = blockIdx.x * blockDim.x + threadIdx.x;
    if (e >= E) return;
    atomicAdd(&g_Mh[idx_out[e] * NIN + idx_in[e]], __float2half(1.0f));
}

// ---------------------------------------------------------------------------
// Kernel 3: HMMA GEMM, cp.async double-buffered.
// Block = 256 threads (8 warps), D tile 128o x 128bc, K range KPB=256 in
// 4 chunks of 64. One __syncthreads per chunk; chunk c+1 loads overlap
// chunk c MMAs. Epilogue RED-adds into out (bc-major, zeroed by qc_zero).
// ---------------------------------------------------------------------------
__global__ void __launch_bounds__(256, 1) qc_gemm_mma(float* __restrict__ out) {
    extern __shared__ __half sm[];
    // 2-stage buffers: [stage][A | Bh | Bl], each 128 x ROWH halves
    int t    = threadIdx.x;
    int wid  = t >> 5;
    int lane = t & 31;
    int mt_b = blockIdx.x & 7;
    int ks   = blockIdx.x >> 3;
    int o0   = mt_b * 128;
    int k0   = ks * KPB;
    int wo   = (wid >> 1) * 32;      // warp o offset (0/32/64/96)
    int n0w  = (wid & 1) * 64;       // warp bc offset (0/64)

    uint32_t sbase = smem_u32(sm);
    uint32_t sA[2], sBh[2], sBl[2];
    #pragma unroll
    for (int s = 0; s < 2; s++) {
        sA[s]  = sbase + (s * 3 + 0) * TILEH * 2;
        sBh[s] = sbase + (s * 3 + 1) * TILEH * 2;
        sBl[s] = sbase + (s * 3 + 2) * TILEH * 2;
    }

    // per-thread copy coordinates: 4 segments of 16B for each tile
    int crow[4], ccol[4];
    #pragma unroll
    for (int j = 0; j < 4; j++) {
        int seg = t + j * 256;       // 0..1023
        crow[j] = seg >> 3;
        ccol[j] = seg & 7;
    }

    // issue chunk 0
    {
        int kc0 = k0;
        #pragma unroll
        for (int j = 0; j < 4; j++) {
            int off = crow[j] * 144 + ccol[j] * 16;
            cp16(sA[0]  + off, &g_Mh [(o0 + crow[j]) * NIN + kc0 + ccol[j] * 8]);
            cp16(sBh[0] + off, &g_ghi[crow[j] * NIN + kc0 + ccol[j] * 8]);
            cp16(sBl[0] + off, &g_glo[crow[j] * NIN + kc0 + ccol[j] * 8]);
        }
        cp_commit();
    }

    float acc[2][8][4];
    #pragma unroll
    for (int i = 0; i < 2; i++)
        #pragma unroll
        for (int j = 0; j < 8; j++)
            #pragma unroll
            for (int q = 0; q < 4; q++) acc[i][j][q] = 0.f;

    for (int c = 0; c < NCHUNK; c++) {
        int buf = c & 1;
        cp_wait0();              // chunk c landed
        __syncthreads();         // + all warps done computing chunk c-1

        if (c + 1 < NCHUNK) {    // prefetch c+1 into other buffer (overlaps MMA)
            int kc1 = k0 + (c + 1) * KC;
            int nb  = buf ^ 1;
            #pragma unroll
            for (int j = 0; j < 4; j++) {
                int off = crow[j] * 144 + ccol[j] * 16;
                cp16(sA[nb]  + off, &g_Mh [(o0 + crow[j]) * NIN + kc1 + ccol[j] * 8]);
                cp16(sBh[nb] + off, &g_ghi[crow[j] * NIN + kc1 + ccol[j] * 8]);
                cp16(sBl[nb] + off, &g_glo[crow[j] * NIN + kc1 + ccol[j] * 8]);
            }
            cp_commit();
        }

        #pragma unroll
        for (int kk = 0; kk < KC; kk += 16) {
            uint32_t a[2][4];
            #pragma unroll
            for (int mt = 0; mt < 2; mt++)
                ldsm_x4(a[mt], sA[buf] + 2 * ((wo + mt * 16 + (lane & 15)) * ROWH
                                              + kk + (lane >> 4) * 8));
            #pragma unroll
            for (int h = 0; h < 2; h++) {
                uint32_t sB = h ? sBl[buf] : sBh[buf];
                #pragma unroll
                for (int ng = 0; ng < 4; ng++) {
                    uint32_t b[4];
                    ldsm_x4(b, sB + 2 * ((n0w + ng * 16 + (lane & 15)) * ROWH
                                          + kk + (lane >> 4) * 8));
                    #pragma unroll
                    for (int mt = 0; mt < 2; mt++) {
                        mma16816(acc[mt][ng * 2 + 0], a[mt], b[0], b[2]);
                        mma16816(acc[mt][ng * 2 + 1], a[mt], b[1], b[3]);
                    }
                }
            }
        }
    }

    // Epilogue: RED straight into out[bc*NOUT + o].
    #pragma unroll
    for (int mt = 0; mt < 2; mt++) {
        #pragma unroll
        for (int nt = 0; nt < 8; nt++) {
            int o  = o0 + wo + mt * 16 + (lane >> 2);
            int bc = n0w + nt * 8 + (lane & 3) * 2;
            atomicAdd(&out[bc * NOUT + o],             acc[mt][nt][0]);
            atomicAdd(&out[(bc + 1) * NOUT + o],       acc[mt][nt][1]);
            atomicAdd(&out[bc * NOUT + o + 8],         acc[mt][nt][2]);
            atomicAdd(&out[(bc + 1) * NOUT + o + 8],   acc[mt][nt][3]);
        }
    }
}

// ---------------------------------------------------------------------------
extern "C" void kernel_launch(void* const* d_in, const int* in_sizes, int n_in,
                              void* d_out, int out_size) {
    const float* features = (const float*)d_in[0];   // (4,32,4096) f32
    const float* G        = (const float*)d_in[1];   // (32,32)     f32
    const int*   idx_out  = (const int*)d_in[2];     // (E,) i32
    const int*   idx_in   = (const int*)d_in[3];     // (E,) i32
    float*       out      = (float*)d_out;           // (4,32,1024) f32
    int E = in_sizes[2];

    static const int GEMM_SMEM = 6 * TILEH * (int)sizeof(__half);  // 110592
    cudaFuncSetAttribute(qc_gemm_mma,
                         cudaFuncAttributeMaxDynamicSharedMemorySize, GEMM_SMEM);

    qc_zero<<<ZVEC_ALL / 256, 256>>>(out);
    qc_transform<<<64, 256>>>(features, G);
    qc_count<<<(E + 255) / 256, 256>>>(idx_out, idx_in, E);
    qc_gemm_mma<<<MTILES * KSPLIT, 256, GEMM_SMEM>>>(out);
}

// round 10
// speedup vs baseline: 1.1429x; 1.1083x over previous
#include <cuda_runtime.h>
#include <cuda_fp16.h>
#include <cstdint>

// ---------------- problem constants ----------------
#define NIN   4096
#define NOUT  1024
#define BC    128          // B*C = 4*32
#define C_DIM 32

// GEMM: D[o(1024), bc(128)] = sum_k M[o,k] * gftT[bc,k]
// CTA tile: 128 o x 64 bc; grid = 8 (o) x 2 (bc) x 16 (K-split) = 256 CTAs
#define KSPLIT 16
#define KPB    (NIN / KSPLIT)   // 256
#define KC     64               // k per smem chunk
#define NCHUNK (KPB / KC)       // 4
#define ROWH   72               // smem row stride in halves (144B = 9x16B)
#define ATILEH (128 * ROWH)     // A tile halves
#define BTILEH (64  * ROWH)     // B tile halves
#define STAGEH (ATILEH + 2 * BTILEH)   // halves per stage

// zero coverage: M = 4M halves = 524288 uint4; out = 131072 f32 = 32768 uint4
#define ZVEC_M   524288
#define ZVEC_ALL (ZVEC_M + 32768)   // 557056 -> 2176 blocks x 256
#define XFORM_BLKS 64

// ---------------- device scratch ----------------
__device__ __align__(16) __half g_Mh[NOUT * NIN];  // 8.4 MB count matrix (fp16)
__device__ __align__(16) __half g_ghi[BC * NIN];   // 1 MB  (G@F)^T hi (fp16)
__device__ __align__(16) __half g_glo[BC * NIN];   // 1 MB  (G@F)^T lo (fp16)

__device__ __forceinline__ uint32_t smem_u32(const void* p) {
    uint32_t a;
    asm("{ .reg .u64 t; cvta.to.shared.u64 t, %1; cvt.u32.u64 %0, t; }" : "=r"(a) : "l"(p));
    return a;
}
__device__ __forceinline__ void cp16(uint32_t dst, const void* src) {
    asm volatile("cp.async.cg.shared.global [%0], [%1], 16;" :: "r"(dst), "l"(src));
}
__device__ __forceinline__ void cp_commit() {
    asm volatile("cp.async.commit_group;" ::: "memory");
}
__device__ __forceinline__ void cp_wait0() {
    asm volatile("cp.async.wait_group 0;" ::: "memory");
}
__device__ __forceinline__ void ldsm_x4(uint32_t* r, uint32_t addr) {
    asm volatile("ldmatrix.sync.aligned.m8n8.x4.shared.b16 {%0,%1,%2,%3}, [%4];"
                 : "=r"(r[0]), "=r"(r[1]), "=r"(r[2]), "=r"(r[3]) : "r"(addr));
}
__device__ __forceinline__ void mma16816(float* c, const uint32_t* a,
                                         uint32_t b0, uint32_t b1) {
    asm volatile(
        "mma.sync.aligned.m16n8k16.row.col.f32.f16.f16.f32 "
        "{%0,%1,%2,%3}, {%4,%5,%6,%7}, {%8,%9}, {%0,%1,%2,%3};"
        : "+f"(c[0]), "+f"(c[1]), "+f"(c[2]), "+f"(c[3])
        : "r"(a[0]), "r"(a[1]), "r"(a[2]), "r"(a[3]), "r"(b0), "r"(b1));
}

// ---------------------------------------------------------------------------
// Kernel 1: fused [zero M + zero out] and [channel-GEMM -> gftT hi/lo].
// Blocks 0..63: transform (4 b x 16 n-tiles). Blocks 64..2239: zeroing.
// ---------------------------------------------------------------------------
__global__ void qc_prep(const float* __restrict__ F, const float* __restrict__ G,
                        float* __restrict__ out) {
    __shared__ float Fs[C_DIM * 256];
    __shared__ float Gs[C_DIM * 33];
    int t = threadIdx.x;

    if (blockIdx.x >= XFORM_BLKS) {
        int gt = (blockIdx.x - XFORM_BLKS) * 256 + t;
        uint4 z = make_uint4(0u, 0u, 0u, 0u);
        if (gt < ZVEC_M)
            reinterpret_cast<uint4*>(g_Mh)[gt] = z;
        else
            reinterpret_cast<uint4*>(out)[gt - ZVEC_M] = z;
        return;
    }

    int b  = blockIdx.x >> 4;
    int n0 = (blockIdx.x & 15) * 256;

    #pragma unroll
    for (int j = 0; j < 32; j++) {
        int idx = t + j * 256;                       // idx = i*256 + nl
        Fs[idx] = F[b * (C_DIM * NIN) + (idx >> 8) * NIN + n0 + (idx & 255)];
    }
    #pragma unroll
    for (int j = 0; j < 4; j++) {
        int idx = t + j * 256;
        Gs[(idx >> 5) * 33 + (idx & 31)] = G[idx];
    }
    __syncthreads();

    #pragma unroll 4
    for (int oc = 0; oc < 32; oc++) {
        float s = 0.f;
        #pragma unroll
        for (int i = 0; i < 32; i++)
            s = fmaf(Gs[oc * 33 + i], Fs[i * 256 + t], s);
        __half h = __float2half_rn(s);
        __half l = __float2half_rn(s - __half2float(h));
        int row = b * 32 + oc;
        g_ghi[row * NIN + n0 + t] = h;
        g_glo[row * NIN + n0 + t] = l;
    }
}

// ---------------------------------------------------------------------------
// Kernel 2: build count matrix. Thread per edge, spread fp16 atomics (RED.F16).
// ---------------------------------------------------------------------------
__global__ void qc_count(const int* __restrict__ idx_out,
                         const int* __restrict__ idx_in, int E) {
    int e = blockIdx.x * blockDim.x + threadIdx.x;
    if (e >= E) return;
    atomicAdd(&g_Mh[idx_out[e] * NIN + idx_in[e]], __float2half(1.0f));
}

// ---------------------------------------------------------------------------
// Kernel 3: HMMA GEMM, cp.async double-buffered, 2 CTAs/SM.
// CTA = 256 threads (8 warps, 4 o-groups x 2 bc-groups), tile 128o x 64bc.
// Epilogue RED-adds into out (bc-major, zeroed by qc_prep).
// ---------------------------------------------------------------------------
__global__ void __launch_bounds__(256, 2) qc_gemm_mma(float* __restrict__ out) {
    extern __shared__ __half sm[];
    int t    = threadIdx.x;
    int wid  = t >> 5;
    int lane = t & 31;
    int bid  = blockIdx.x;
    int mt_b = bid & 7;              // o tile
    int nb   = (bid >> 3) & 1;       // bc half
    int ks   = bid >> 4;             // K split
    int o0   = mt_b * 128;
    int bc0  = nb * 64;
    int k0   = ks * KPB;
    int wo   = (wid >> 1) * 32;      // warp o offset (0/32/64/96)
    int n0w  = (wid & 1) * 32;       // warp bc offset within CTA (0/32)

    uint32_t sbase = smem_u32(sm);
    uint32_t sA[2], sBh[2], sBl[2];
    #pragma unroll
    for (int s = 0; s < 2; s++) {
        sA[s]  = sbase + (s * STAGEH) * 2;
        sBh[s] = sA[s] + ATILEH * 2;
        sBl[s] = sBh[s] + BTILEH * 2;
    }

    // prefetch helper: A 1024 segs (4/thr), Bh/Bl 512 segs (2/thr) of 16B
    auto prefetch = [&](int stage, int kc) {
        #pragma unroll
        for (int j = 0; j < 4; j++) {
            int seg = t + j * 256;                 // 0..1023
            int row = seg >> 3, col = seg & 7;
            cp16(sA[stage] + row * 144 + col * 16,
                 &g_Mh[(o0 + row) * NIN + kc + col * 8]);
        }
        #pragma unroll
        for (int j = 0; j < 2; j++) {
            int seg = t + j * 256;                 // 0..511
            int row = seg >> 3, col = seg & 7;
            int off = row * 144 + col * 16;
            const int gr = (bc0 + row) * NIN + kc + col * 8;
            cp16(sBh[stage] + off, &g_ghi[gr]);
            cp16(sBl[stage] + off, &g_glo[gr]);
        }
        cp_commit();
    };

    prefetch(0, k0);

    float acc[2][4][4];
    #pragma unroll
    for (int i = 0; i < 2; i++)
        #pragma unroll
        for (int j = 0; j < 4; j++)
            #pragma unroll
            for (int q = 0; q < 4; q++) acc[i][j][q] = 0.f;

    for (int c = 0; c < NCHUNK; c++) {
        int buf = c & 1;
        cp_wait0();
        __syncthreads();

        if (c + 1 < NCHUNK) prefetch(buf ^ 1, k0 + (c + 1) * KC);

        #pragma unroll
        for (int kk = 0; kk < KC; kk += 16) {
            uint32_t a[2][4];
            #pragma unroll
            for (int mt = 0; mt < 2; mt++)
                ldsm_x4(a[mt], sA[buf] + 2 * ((wo + mt * 16 + (lane & 15)) * ROWH
                                              + kk + (lane >> 4) * 8));
            #pragma unroll
            for (int h = 0; h < 2; h++) {
                uint32_t sB = h ? sBl[buf] : sBh[buf];
                #pragma unroll
                for (int ng = 0; ng < 2; ng++) {
                    uint32_t b[4];
                    ldsm_x4(b, sB + 2 * ((n0w + ng * 16 + (lane & 15)) * ROWH
                                          + kk + (lane >> 4) * 8));
                    #pragma unroll
                    for (int mt = 0; mt < 2; mt++) {
                        mma16816(acc[mt][ng * 2 + 0], a[mt], b[0], b[2]);
                        mma16816(acc[mt][ng * 2 + 1], a[mt], b[1], b[3]);
                    }
                }
            }
        }
    }

    // Epilogue: RED into out[bc*NOUT + o]. Frag rows = lane>>2 (+8),
    // cols = (lane&3)*2 + {0,1}.
    #pragma unroll
    for (int mt = 0; mt < 2; mt++) {
        #pragma unroll
        for (int nt = 0; nt < 4; nt++) {
            int o  = o0 + wo + mt * 16 + (lane >> 2);
            int bc = bc0 + n0w + nt * 8 + (lane & 3) * 2;
            atomicAdd(&out[bc * NOUT + o],             acc[mt][nt][0]);
            atomicAdd(&out[(bc + 1) * NOUT + o],       acc[mt][nt][1]);
            atomicAdd(&out[bc * NOUT + o + 8],         acc[mt][nt][2]);
            atomicAdd(&out[(bc + 1) * NOUT + o + 8],   acc[mt][nt][3]);
        }
    }
}

// ---------------------------------------------------------------------------
extern "C" void kernel_launch(void* const* d_in, const int* in_sizes, int n_in,
                              void* d_out, int out_size) {
    const float* features = (const float*)d_in[0];   // (4,32,4096) f32
    const float* G        = (const float*)d_in[1];   // (32,32)     f32
    const int*   idx_out  = (const int*)d_in[2];     // (E,) i32
    const int*   idx_in   = (const int*)d_in[3];     // (E,) i32
    float*       out      = (float*)d_out;           // (4,32,1024) f32
    int E = in_sizes[2];

    static const int GEMM_SMEM = 2 * STAGEH * (int)sizeof(__half);  // 73728
    cudaFuncSetAttribute(qc_gemm_mma,
                         cudaFuncAttributeMaxDynamicSharedMemorySize, GEMM_SMEM);

    qc_prep<<<XFORM_BLKS + ZVEC_ALL / 256, 256>>>(features, G, out);
    qc_count<<<(E + 255) / 256, 256>>>(idx_out, idx_in, E);
    qc_gemm_mma<<<8 * 2 * KSPLIT, 256, GEMM_SMEM>>>(out);
}

// round 11
// speedup vs baseline: 1.2234x; 1.0705x over previous
#include <cuda_runtime.h>
#include <cuda_fp16.h>
#include <cstdint>

// ---------------- problem constants ----------------
#define NIN   4096
#define NOUT  1024
#define BC    128          // B*C = 4*32
#define C_DIM 32

// GEMM: D[o(1024), bc(128)] = sum_k M[o,k] * gftT[bc,k]
// CTA tile: 128 o x 64 bc; grid = 8 (o) x 2 (bc) x 16 (K-split) = 256 CTAs
#define KSPLIT 16
#define KPB    (NIN / KSPLIT)   // 256
#define KC     64               // k per smem chunk
#define NCHUNK (KPB / KC)       // 4
#define ROWH   72               // smem row stride in halves (144B = 9x16B)
#define ATILEH (128 * ROWH)     // A tile halves
#define BTILEH (64  * ROWH)     // B tile halves
#define STAGEH (ATILEH + 2 * BTILEH)   // halves per stage

// zero coverage: M = 4M halves = 524288 uint4; out = 131072 f32 = 32768 uint4
#define ZVEC_M   524288
#define ZVEC_ALL (ZVEC_M + 32768)   // 557056 -> 2176 blocks x 256
#define XFORM_BLKS 256              // 4 b x 64 n-tiles of 64

// ---------------- device scratch ----------------
__device__ __align__(16) __half g_Mh[NOUT * NIN];  // 8.4 MB count matrix (fp16)
__device__ __align__(16) __half g_ghi[BC * NIN];   // 1 MB  (G@F)^T hi (fp16)
__device__ __align__(16) __half g_glo[BC * NIN];   // 1 MB  (G@F)^T lo (fp16)

__device__ __forceinline__ uint32_t smem_u32(const void* p) {
    uint32_t a;
    asm("{ .reg .u64 t; cvta.to.shared.u64 t, %1; cvt.u32.u64 %0, t; }" : "=r"(a) : "l"(p));
    return a;
}
__device__ __forceinline__ void cp16(uint32_t dst, const void* src) {
    asm volatile("cp.async.cg.shared.global [%0], [%1], 16;" :: "r"(dst), "l"(src));
}
__device__ __forceinline__ void cp_commit() {
    asm volatile("cp.async.commit_group;" ::: "memory");
}
__device__ __forceinline__ void cp_wait0() {
    asm volatile("cp.async.wait_group 0;" ::: "memory");
}
__device__ __forceinline__ void ldsm_x4(uint32_t* r, uint32_t addr) {
    asm volatile("ldmatrix.sync.aligned.m8n8.x4.shared.b16 {%0,%1,%2,%3}, [%4];"
                 : "=r"(r[0]), "=r"(r[1]), "=r"(r[2]), "=r"(r[3]) : "r"(addr));
}
__device__ __forceinline__ void mma16816(float* c, const uint32_t* a,
                                         uint32_t b0, uint32_t b1) {
    asm volatile(
        "mma.sync.aligned.m16n8k16.row.col.f32.f16.f16.f32 "
        "{%0,%1,%2,%3}, {%4,%5,%6,%7}, {%8,%9}, {%0,%1,%2,%3};"
        : "+f"(c[0]), "+f"(c[1]), "+f"(c[2]), "+f"(c[3])
        : "r"(a[0]), "r"(a[1]), "r"(a[2]), "r"(a[3]), "r"(b0), "r"(b1));
}

// ---------------------------------------------------------------------------
// Kernel 1: fused [zero M + zero out] and [channel-GEMM -> gftT hi/lo].
// Blocks 0..255: transform (4 b x 64 n-tiles of 64 each, widened 4x vs R10).
// Blocks 256..2431: zeroing (one uint4 per thread).
// ---------------------------------------------------------------------------
__global__ void qc_prep(const float* __restrict__ F, const float* __restrict__ G,
                        float* __restrict__ out) {
    __shared__ float Fs[C_DIM * 64];
    __shared__ float Gs[C_DIM * 33];
    int t = threadIdx.x;

    if (blockIdx.x >= XFORM_BLKS) {
        int gt = (blockIdx.x - XFORM_BLKS) * 256 + t;
        uint4 z = make_uint4(0u, 0u, 0u, 0u);
        if (gt < ZVEC_M)
            reinterpret_cast<uint4*>(g_Mh)[gt] = z;
        else
            reinterpret_cast<uint4*>(out)[gt - ZVEC_M] = z;
        return;
    }

    int b  = blockIdx.x >> 6;          // 0..3
    int n0 = (blockIdx.x & 63) * 64;   // n tile start

    // Stage F tile 32 x 64 (2048 floats, 8 per thread, coalesced along n)
    #pragma unroll
    for (int j = 0; j < 8; j++) {
        int idx = t + j * 256;                       // idx = i*64 + nl
        Fs[idx] = F[b * (C_DIM * NIN) + (idx >> 6) * NIN + n0 + (idx & 63)];
    }
    #pragma unroll
    for (int j = 0; j < 4; j++) {
        int idx = t + j * 256;
        Gs[(idx >> 5) * 33 + (idx & 31)] = G[idx];
    }
    __syncthreads();

    int nl  = t & 63;        // n within tile
    int ocg = t >> 6;        // 0..3 -> oc group of 8

    #pragma unroll
    for (int oo = 0; oo < 8; oo++) {
        int oc = ocg * 8 + oo;
        float s = 0.f;
        #pragma unroll
        for (int i = 0; i < 32; i++)
            s = fmaf(Gs[oc * 33 + i], Fs[i * 64 + nl], s);
        __half h = __float2half_rn(s);
        __half l = __float2half_rn(s - __half2float(h));
        int row = b * 32 + oc;
        g_ghi[row * NIN + n0 + nl] = h;
        g_glo[row * NIN + n0 + nl] = l;
    }
}

// ---------------------------------------------------------------------------
// Kernel 2: build count matrix. Thread per edge, spread fp16 atomics (RED.F16).
// ---------------------------------------------------------------------------
__global__ void qc_count(const int* __restrict__ idx_out,
                         const int* __restrict__ idx_in, int E) {
    int e = blockIdx.x * blockDim.x + threadIdx.x;
    if (e >= E) return;
    atomicAdd(&g_Mh[idx_out[e] * NIN + idx_in[e]], __float2half(1.0f));
}

// ---------------------------------------------------------------------------
// Kernel 3: HMMA GEMM, cp.async double-buffered, 2 CTAs/SM.
// CTA = 256 threads (8 warps, 4 o-groups x 2 bc-groups), tile 128o x 64bc.
// Epilogue RED-adds into out (bc-major, zeroed by qc_prep).
// ---------------------------------------------------------------------------
__global__ void __launch_bounds__(256, 2) qc_gemm_mma(float* __restrict__ out) {
    extern __shared__ __half sm[];
    int t    = threadIdx.x;
    int wid  = t >> 5;
    int lane = t & 31;
    int bid  = blockIdx.x;
    int mt_b = bid & 7;              // o tile
    int nb   = (bid >> 3) & 1;       // bc half
    int ks   = bid >> 4;             // K split
    int o0   = mt_b * 128;
    int bc0  = nb * 64;
    int k0   = ks * KPB;
    int wo   = (wid >> 1) * 32;      // warp o offset (0/32/64/96)
    int n0w  = (wid & 1) * 32;       // warp bc offset within CTA (0/32)

    uint32_t sbase = smem_u32(sm);
    uint32_t sA[2], sBh[2], sBl[2];
    #pragma unroll
    for (int s = 0; s < 2; s++) {
        sA[s]  = sbase + (s * STAGEH) * 2;
        sBh[s] = sA[s] + ATILEH * 2;
        sBl[s] = sBh[s] + BTILEH * 2;
    }

    // prefetch helper: A 1024 segs (4/thr), Bh/Bl 512 segs (2/thr) of 16B
    auto prefetch = [&](int stage, int kc) {
        #pragma unroll
        for (int j = 0; j < 4; j++) {
            int seg = t + j * 256;                 // 0..1023
            int row = seg >> 3, col = seg & 7;
            cp16(sA[stage] + row * 144 + col * 16,
                 &g_Mh[(o0 + row) * NIN + kc + col * 8]);
        }
        #pragma unroll
        for (int j = 0; j < 2; j++) {
            int seg = t + j * 256;                 // 0..511
            int row = seg >> 3, col = seg & 7;
            int off = row * 144 + col * 16;
            const int gr = (bc0 + row) * NIN + kc + col * 8;
            cp16(sBh[stage] + off, &g_ghi[gr]);
            cp16(sBl[stage] + off, &g_glo[gr]);
        }
        cp_commit();
    };

    prefetch(0, k0);

    float acc[2][4][4];
    #pragma unroll
    for (int i = 0; i < 2; i++)
        #pragma unroll
        for (int j = 0; j < 4; j++)
            #pragma unroll
            for (int q = 0; q < 4; q++) acc[i][j][q] = 0.f;

    for (int c = 0; c < NCHUNK; c++) {
        int buf = c & 1;
        cp_wait0();
        __syncthreads();

        if (c + 1 < NCHUNK) prefetch(buf ^ 1, k0 + (c + 1) * KC);

        #pragma unroll
        for (int kk = 0; kk < KC; kk += 16) {
            uint32_t a[2][4];
            #pragma unroll
            for (int mt = 0; mt < 2; mt++)
                ldsm_x4(a[mt], sA[buf] + 2 * ((wo + mt * 16 + (lane & 15)) * ROWH
                                              + kk + (lane >> 4) * 8));
            #pragma unroll
            for (int h = 0; h < 2; h++) {
                uint32_t sB = h ? sBl[buf] : sBh[buf];
                #pragma unroll
                for (int ng = 0; ng < 2; ng++) {
                    uint32_t b[4];
                    ldsm_x4(b, sB + 2 * ((n0w + ng * 16 + (lane & 15)) * ROWH
                                          + kk + (lane >> 4) * 8));
                    #pragma unroll
                    for (int mt = 0; mt < 2; mt++) {
                        mma16816(acc[mt][ng * 2 + 0], a[mt], b[0], b[2]);
                        mma16816(acc[mt][ng * 2 + 1], a[mt], b[1], b[3]);
                    }
                }
            }
        }
    }

    // Epilogue: RED into out[bc*NOUT + o]. Frag rows = lane>>2 (+8),
    // cols = (lane&3)*2 + {0,1}.
    #pragma unroll
    for (int mt = 0; mt < 2; mt++) {
        #pragma unroll
        for (int nt = 0; nt < 4; nt++) {
            int o  = o0 + wo + mt * 16 + (lane >> 2);
            int bc = bc0 + n0w + nt * 8 + (lane & 3) * 2;
            atomicAdd(&out[bc * NOUT + o],             acc[mt][nt][0]);
            atomicAdd(&out[(bc + 1) * NOUT + o],       acc[mt][nt][1]);
            atomicAdd(&out[bc * NOUT + o + 8],         acc[mt][nt][2]);
            atomicAdd(&out[(bc + 1) * NOUT + o + 8],   acc[mt][nt][3]);
        }
    }
}

// ---------------------------------------------------------------------------
extern "C" void kernel_launch(void* const* d_in, const int* in_sizes, int n_in,
                              void* d_out, int out_size) {
    const float* features = (const float*)d_in[0];   // (4,32,4096) f32
    const float* G        = (const float*)d_in[1];   // (32,32)     f32
    const int*   idx_out  = (const int*)d_in[2];     // (E,) i32
    const int*   idx_in   = (const int*)d_in[3];     // (E,) i32
    float*       out      = (float*)d_out;           // (4,32,1024) f32
    int E = in_sizes[2];

    static const int GEMM_SMEM = 2 * STAGEH * (int)sizeof(__half);  // 73728
    cudaFuncSetAttribute(qc_gemm_mma,
                         cudaFuncAttributeMaxDynamicSharedMemorySize, GEMM_SMEM);

    qc_prep<<<XFORM_BLKS + ZVEC_ALL / 256, 256>>>(features, G, out);
    qc_count<<<(E + 255) / 256, 256>>>(idx_out, idx_in, E);
    qc_gemm_mma<<<8 * 2 * KSPLIT, 256, GEMM_SMEM>>>(out);
}